// round 11
// baseline (speedup 1.0000x reference)
#include <cuda_runtime.h>
#include <cstdint>

#define NMAX   30000
#define DREP   256
#define KCAPS  8
#define DDIM   32
#define MNBR   16
#define NFEAT  1024
#define NCLS   16
#define USTR   36   // u_s row stride (floats)

// ---------------- device scratch (static, allocation-free) ----------------
__device__ float g_bufA[NMAX * DREP];
__device__ float g_bufB[NMAX * DREP];
__device__ float g_bufC[NMAX * DREP];

__device__ __forceinline__ float wsum32(float v) {
    v += __shfl_xor_sync(0xffffffffu, v, 16);
    v += __shfl_xor_sync(0xffffffffu, v, 8);
    v += __shfl_xor_sync(0xffffffffu, v, 4);
    v += __shfl_xor_sync(0xffffffffu, v, 2);
    v += __shfl_xor_sync(0xffffffffu, v, 1);
    return v;
}

// packed f32x2 helpers (Blackwell sm_103a)
__device__ __forceinline__ unsigned long long dup2(float x) {
    unsigned long long r;
    asm("mov.b64 %0, {%1, %1};" : "=l"(r) : "f"(x));
    return r;
}
__device__ __forceinline__ void ffma2(unsigned long long& d,
                                      unsigned long long a, unsigned long long b) {
    asm("fma.rn.f32x2 %0, %1, %2, %0;" : "+l"(d) : "l"(a), "l"(b));
}
__device__ __forceinline__ void unpack2(unsigned long long v, float& lo, float& hi) {
    asm("mov.b64 {%0, %1}, %2;" : "=f"(lo), "=f"(hi) : "l"(v));
}

// ---------------- PCA: out = relu(A[M,1024] @ W[1024,256] + b) ----------------
__global__ void __launch_bounds__(256) pca_kernel(
    const float* __restrict__ A, const float* __restrict__ W,
    const float* __restrict__ bias, float* __restrict__ out, int M)
{
    __shared__ __align__(16) float As[16][128];
    __shared__ __align__(16) float Bs[16][128];

    const int tid = threadIdx.x;
    const int bm  = blockIdx.x * 128;
    const int bn  = blockIdx.y * 128;
    const int ty  = tid >> 4;
    const int tx  = tid & 15;

    const int arow = tid & 127;
    const int kb   = (tid >> 7) * 8;
    const int brow = tid >> 5;
    const int bcol = (tid & 31) * 4;

    unsigned long long acc[8][4];
#pragma unroll
    for (int i = 0; i < 8; i++)
#pragma unroll
        for (int j = 0; j < 4; j++) acc[i][j] = 0ull;

    const bool aok = (bm + arow) < M;
    const float* Aptr = A + (size_t)(bm + arow) * NFEAT + kb;
    const float* Wptr = W + (size_t)brow * DREP + bn + bcol;

    float4 a0 = make_float4(0.f, 0.f, 0.f, 0.f), a1 = a0;
    if (aok) { a0 = *(const float4*)(Aptr); a1 = *(const float4*)(Aptr + 4); }
    float4 b0 = *(const float4*)(Wptr);
    float4 b1 = *(const float4*)(Wptr + (size_t)8 * DREP);

    for (int k0 = 0; k0 < NFEAT; k0 += 16) {
        __syncthreads();
        As[kb + 0][arow] = a0.x; As[kb + 1][arow] = a0.y;
        As[kb + 2][arow] = a0.z; As[kb + 3][arow] = a0.w;
        As[kb + 4][arow] = a1.x; As[kb + 5][arow] = a1.y;
        As[kb + 6][arow] = a1.z; As[kb + 7][arow] = a1.w;
        *(float4*)&Bs[brow][bcol]     = b0;
        *(float4*)&Bs[brow + 8][bcol] = b1;
        __syncthreads();

        const int kn = k0 + 16;
        if (kn < NFEAT) {
            if (aok) {
                a0 = *(const float4*)(Aptr + kn);
                a1 = *(const float4*)(Aptr + kn + 4);
            }
            b0 = *(const float4*)(Wptr + (size_t)kn * DREP);
            b1 = *(const float4*)(Wptr + (size_t)(kn + 8) * DREP);
        }

#pragma unroll
        for (int kk = 0; kk < 16; kk++) {
            float ra[8];
            *(float4*)(ra)     = *(const float4*)&As[kk][ty * 8];
            *(float4*)(ra + 4) = *(const float4*)&As[kk][ty * 8 + 4];
            ulonglong2 rbl = *(const ulonglong2*)&Bs[kk][tx * 8];
            ulonglong2 rbh = *(const ulonglong2*)&Bs[kk][tx * 8 + 4];
            unsigned long long rb[4] = { rbl.x, rbl.y, rbh.x, rbh.y };
#pragma unroll
            for (int i = 0; i < 8; i++) {
                unsigned long long a2 = dup2(ra[i]);
#pragma unroll
                for (int j = 0; j < 4; j++) ffma2(acc[i][j], a2, rb[j]);
            }
        }
    }

#pragma unroll
    for (int i = 0; i < 8; i++) {
        int row = bm + ty * 8 + i;
        if (row < M) {
#pragma unroll
            for (int j = 0; j < 4; j++) {
                float lo, hi;
                unpack2(acc[i][j], lo, hi);
                int col = bn + tx * 8 + j * 2;
                out[(size_t)row * DREP + col]     = fmaxf(lo + bias[col], 0.f);
                out[(size_t)row * DREP + col + 1] = fmaxf(hi + bias[col + 1], 0.f);
            }
        }
    }
}

// -------- layer-0: per-capsule l2norm -> fc (32x32 per capsule) -> relu -> l2norm --------
__global__ void __launch_bounds__(256) fcnorm_kernel(
    const float* __restrict__ hin, const float* __restrict__ fc_w,
    const float* __restrict__ fc_b, float* __restrict__ znorm, int N)
{
    __shared__ float wt[KCAPS * DDIM * DDIM];
    __shared__ float bs[KCAPS * DDIM];

    const int tid = threadIdx.x;
    for (int idx = tid; idx < KCAPS * DDIM * DDIM; idx += 256) {
        int k = idx >> 10;
        int o = (idx >> 5) & 31;
        int i = idx & 31;
        wt[k * 1024 + i * 32 + o] = fc_w[idx];
    }
    bs[tid] = fc_b[tid];
    __syncthreads();

    const int k = tid >> 5, lane = tid & 31;
    int node0 = blockIdx.x * 8;
    for (int nn = 0; nn < 8; nn++) {
        int node = node0 + nn;
        if (node >= N) break;
        float v = hin[(size_t)node * DREP + tid];
        float s = wsum32(v * v);
        float xn = v / fmaxf(sqrtf(s), 1e-12f);
        float y = bs[tid];
        const float* wk = &wt[k * 1024];
#pragma unroll
        for (int i = 0; i < 32; i++) {
            float xi = __shfl_sync(0xffffffffu, xn, i);
            y = fmaf(xi, wk[i * 32 + lane], y);
        }
        y = fmaxf(y, 0.f);
        float s2 = wsum32(y * y);
        znorm[(size_t)node * DREP + tid] = y / fmaxf(sqrtf(s2), 1e-12f);
    }
}

// ---------------- routing v5: dual-layout register residency ----------------
// One CTA (256 thr) per node. warp = capsule k.
//   zcol[m]  : (k, lane=d) layout      -> u-update (16 FMA)
//   zrow[j]  : (k, half, mm) layout    -> p-phase (16 FMA + 1 shfl)
// smem: tiny (u_s, double-buffered p_s, wc_s). One __syncthreads per iter.
__global__ void __launch_bounds__(256) route_kernel(
    const float* __restrict__ znorm, const int* __restrict__ nbrs,
    const float* __restrict__ raw_param, const int* __restrict__ routit_p,
    float* __restrict__ outbuf, int out_mode, int N)
{
    __shared__ __align__(16) float u_s[KCAPS * USTR];
    __shared__ __align__(16) float p_s[2][MNBR * KCAPS];   // [parity][mm*8+k]
    __shared__ __align__(16) float wc_s[KCAPS * MNBR];     // [k*16+mm]

    const int node = blockIdx.x;
    const int tid  = threadIdx.x;
    const int k    = tid >> 5, lane = tid & 31;
    const int half = lane >> 4;          // 0/1 : which 16 d's of the row
    const int mm   = lane & 15;          // neighbor owned in row layout

    const float param = 1.f / (1.f + __expf(-raw_param[0]));
    const float q = 1.f - param;
    const int rt = routit_p ? *routit_p : 6;

    const int nbase = node * MNBR;

    // d-layout gather: zcol[m] = z[nbr_m][k*32 + lane]   (coalesced)
    float zcol[MNBR];
#pragma unroll
    for (int m = 0; m < MNBR; m++) {
        int nb = nbrs[nbase + m];
        zcol[m] = (nb >= 0 && nb < N) ? znorm[(size_t)nb * DREP + tid] : 0.f;
    }
    // row-half gather: zrow = z[nbr_mm][k*32 + half*16 .. +15]  (4x LDG.128)
    float4 zrow[4];
    {
        int nb = nbrs[nbase + mm];
        if (nb >= 0 && nb < N) {
            const float4* src = (const float4*)&znorm[(size_t)nb * DREP + k * 32 + half * 16];
#pragma unroll
            for (int j = 0; j < 4; j++) zrow[j] = src[j];
        } else {
#pragma unroll
            for (int j = 0; j < 4; j++) zrow[j] = make_float4(0.f, 0.f, 0.f, 0.f);
        }
    }
    float ub = znorm[(size_t)node * DREP + tid];

    // iteration 0: p == 0 -> p1 = 1/M, p2 = 1/K
    {
        const float w0 = param * (1.f / 16.f) + q * (1.f / 8.f);
        float a = ub;
#pragma unroll
        for (int m = 0; m < MNBR; m++) a = fmaf(zcol[m], w0, a);
        ub = a;
    }

    for (int it = 1; it < rt; it++) {
        const int buf = it & 1;
        // normalize previous u, publish (same warp produces & consumes u_s[k])
        float s = wsum32(ub * ub);
        float un = ub / fmaxf(sqrtf(s), 1e-12f);
        u_s[k * USTR + lane] = un;
        __syncwarp();

        // p[mm,k] = zrow . un_half, halves joined by one shfl
        const float4* ur = (const float4*)&u_s[k * USTR + half * 16];
        float p = 0.f;
#pragma unroll
        for (int j = 0; j < 4; j++) {
            float4 uv = ur[j];
            p = fmaf(zrow[j].x, uv.x, p);
            p = fmaf(zrow[j].y, uv.y, p);
            p = fmaf(zrow[j].z, uv.z, p);
            p = fmaf(zrow[j].w, uv.w, p);
        }
        p += __shfl_xor_sync(0xffffffffu, p, 16);   // full dot on both halves

        // softmax over neighbors m (p1): 16-lane group within each half
        float mx = p;
        mx = fmaxf(mx, __shfl_xor_sync(0xffffffffu, mx, 1));
        mx = fmaxf(mx, __shfl_xor_sync(0xffffffffu, mx, 2));
        mx = fmaxf(mx, __shfl_xor_sync(0xffffffffu, mx, 4));
        mx = fmaxf(mx, __shfl_xor_sync(0xffffffffu, mx, 8));
        float e1 = __expf(p - mx);
        float es = e1;
        es += __shfl_xor_sync(0xffffffffu, es, 1);
        es += __shfl_xor_sync(0xffffffffu, es, 2);
        es += __shfl_xor_sync(0xffffffffu, es, 4);
        es += __shfl_xor_sync(0xffffffffu, es, 8);
        float p1w = e1 / es;

        // publish p for the cross-capsule softmax (one writer half)
        if (half == 0) p_s[buf][mm * KCAPS + k] = p;
        __syncthreads();

        // softmax over capsules k (p2): 2x LDS.128 row read
        float pv[8];
        *(float4*)(pv)     = *(const float4*)&p_s[buf][mm * KCAPS];
        *(float4*)(pv + 4) = *(const float4*)&p_s[buf][mm * KCAPS + 4];
        float mx2 = pv[0];
#pragma unroll
        for (int j = 1; j < 8; j++) mx2 = fmaxf(mx2, pv[j]);
        float es2 = 0.f;
#pragma unroll
        for (int j = 0; j < 8; j++) es2 += __expf(pv[j] - mx2);
        float p2w = __expf(p - mx2) / es2;

        if (half == 0) wc_s[k * MNBR + mm] = fmaf(param, p1w, q * p2w);
        __syncwarp();   // wc_s[k] written & read by warp k only

        // u update: pure register FMA, wc via broadcast LDS.128
        const float4* wr = (const float4*)&wc_s[k * MNBR];
        float a = ub;
#pragma unroll
        for (int j = 0; j < 4; j++) {
            float4 wv = wr[j];
            a = fmaf(zcol[j * 4 + 0], wv.x, a);
            a = fmaf(zcol[j * 4 + 1], wv.y, a);
            a = fmaf(zcol[j * 4 + 2], wv.z, a);
            a = fmaf(zcol[j * 4 + 3], wv.w, a);
        }
        ub = a;
    }

    if (out_mode == 0) {
        float r = fmaxf(ub, 0.f);
        float s = wsum32(r * r);
        outbuf[(size_t)node * DREP + tid] = r / fmaxf(sqrtf(s), 1e-12f);
    } else {
        outbuf[(size_t)node * DREP + tid] = ub;
    }
}

// ---------------- classifier: logit = h @ mlp_w^T + b; log_softmax; copy h ----------------
__global__ void __launch_bounds__(256) cls_kernel(
    const float* __restrict__ h, const float* __restrict__ mw,
    const float* __restrict__ mb, float* __restrict__ outLogp,
    float* __restrict__ outH, int N)
{
    __shared__ float lgs[8][17];
    const int w = threadIdx.x >> 5, lane = threadIdx.x & 31;
    const int node = blockIdx.x * 8 + w;
    if (node >= N) return;

    float hreg[8];
#pragma unroll
    for (int j = 0; j < 8; j++) hreg[j] = h[(size_t)node * DREP + j * 32 + lane];
    if (outH) {
#pragma unroll
        for (int j = 0; j < 8; j++) outH[(size_t)node * DREP + j * 32 + lane] = hreg[j];
    }

    float logit[NCLS];
#pragma unroll
    for (int c = 0; c < NCLS; c++) {
        float a = 0.f;
#pragma unroll
        for (int j = 0; j < 8; j++)
            a = fmaf(hreg[j], mw[c * DREP + j * 32 + lane], a);
        a += __shfl_xor_sync(0xffffffffu, a, 16);
        a += __shfl_xor_sync(0xffffffffu, a, 8);
        a += __shfl_xor_sync(0xffffffffu, a, 4);
        a += __shfl_xor_sync(0xffffffffu, a, 2);
        a += __shfl_xor_sync(0xffffffffu, a, 1);
        logit[c] = a + mb[c];
    }
    float mx = logit[0];
#pragma unroll
    for (int c = 1; c < NCLS; c++) mx = fmaxf(mx, logit[c]);
    float ssum = 0.f;
#pragma unroll
    for (int c = 0; c < NCLS; c++) ssum += expf(logit[c] - mx);
    float L = mx + logf(ssum);
    if (lane == 0) {
#pragma unroll
        for (int c = 0; c < NCLS; c++) lgs[w][c] = logit[c];
    }
    __syncwarp();
    if (lane < NCLS)
        outLogp[(size_t)node * NCLS + lane] = lgs[w][lane] - L;
}

__global__ void copy_kernel(const float* __restrict__ src, float* __restrict__ dst, int n)
{
    int i = blockIdx.x * blockDim.x + threadIdx.x;
    if (i < n) dst[i] = src[i];
}

// ---------------- launch ----------------
extern "C" void kernel_launch(void* const* d_in, const int* in_sizes, int n_in,
                              void* d_out, int out_size)
{
    const float* x         = (const float*)d_in[0];
    const int*   nbrs      = (const int*)  d_in[1];
    const float* pca_w     = (const float*)d_in[2];
    const float* pca_b     = (const float*)d_in[3];
    const float* raw_param = (const float*)d_in[4];
    const float* fc_w      = (const float*)d_in[5];
    const float* fc_b      = (const float*)d_in[6];
    const float* mlp_w     = (const float*)d_in[7];
    const float* mlp_b     = (const float*)d_in[8];
    const int*   routit    = (n_in > 9) ? (const int*)d_in[9] : nullptr;

    const int N = in_sizes[0] / NFEAT;

    float *bufA, *bufB, *bufC;
    cudaGetSymbolAddress((void**)&bufA, g_bufA);
    cudaGetSymbolAddress((void**)&bufB, g_bufB);
    cudaGetSymbolAddress((void**)&bufC, g_bufC);

    // 1) h0 = relu(x @ pca_w + pca_b)
    dim3 pgrid((N + 127) / 128, DREP / 128);
    pca_kernel<<<pgrid, 256>>>(x, pca_w, pca_b, bufA, N);

    // 2) layer-0 front end: l2norm -> per-capsule fc -> relu -> l2norm
    fcnorm_kernel<<<(N + 7) / 8, 256>>>(bufA, fc_w, fc_b, bufB, N);

    // 3) three routing layers (intermediate relu+l2norm fused in epilogue)
    route_kernel<<<N, 256>>>(bufB, nbrs, raw_param, routit, bufA, 0, N);
    route_kernel<<<N, 256>>>(bufA, nbrs, raw_param, routit, bufB, 0, N);
    route_kernel<<<N, 256>>>(bufB, nbrs, raw_param, routit, bufC, 1, N);

    // 4) classifier + output assembly (adaptive to harness output layout)
    float* out = (float*)d_out;
    if (out_size == N * (NCLS + DREP)) {
        cls_kernel<<<(N + 7) / 8, 256>>>(bufC, mlp_w, mlp_b, out, out + (size_t)N * NCLS, N);
    } else if (out_size == N * NCLS) {
        cls_kernel<<<(N + 7) / 8, 256>>>(bufC, mlp_w, mlp_b, out, nullptr, N);
    } else {
        int n = N * DREP;
        copy_kernel<<<(n + 255) / 256, 256>>>(bufC, out, n);
    }
}

// round 12
// speedup vs baseline: 1.4020x; 1.4020x over previous
#include <cuda_runtime.h>
#include <cstdint>

#define NMAX   30000
#define DREP   256
#define KCAPS  8
#define DDIM   32
#define MNBR   16
#define NFEAT  1024
#define NCLS   16
#define ZSTR   36   // padded row stride (floats): 16B-aligned, conflict-free LDS.128

// ---------------- device scratch (static, allocation-free) ----------------
__device__ float g_bufA[NMAX * DREP];
__device__ float g_bufB[NMAX * DREP];
__device__ float g_bufC[NMAX * DREP];

__device__ __forceinline__ float wsum32(float v) {
    v += __shfl_xor_sync(0xffffffffu, v, 16);
    v += __shfl_xor_sync(0xffffffffu, v, 8);
    v += __shfl_xor_sync(0xffffffffu, v, 4);
    v += __shfl_xor_sync(0xffffffffu, v, 2);
    v += __shfl_xor_sync(0xffffffffu, v, 1);
    return v;
}

// packed f32x2 helpers (Blackwell sm_103a)
__device__ __forceinline__ unsigned long long dup2(float x) {
    unsigned long long r;
    asm("mov.b64 %0, {%1, %1};" : "=l"(r) : "f"(x));
    return r;
}
__device__ __forceinline__ void ffma2(unsigned long long& d,
                                      unsigned long long a, unsigned long long b) {
    asm("fma.rn.f32x2 %0, %1, %2, %0;" : "+l"(d) : "l"(a), "l"(b));
}
__device__ __forceinline__ void unpack2(unsigned long long v, float& lo, float& hi) {
    asm("mov.b64 {%0, %1}, %2;" : "=f"(lo), "=f"(hi) : "l"(v));
}

// ---------------- PCA: out = relu(A[M,1024] @ W[1024,256] + b) ----------------
// 128x128 tile, K-step 16, register-prefetch pipeline, A stored pre-duplicated.
__global__ void __launch_bounds__(256) pca_kernel(
    const float* __restrict__ A, const float* __restrict__ W,
    const float* __restrict__ bias, float* __restrict__ out, int M)
{
    __shared__ __align__(16) float As2[16][256];  // duplicated pairs: As2[k][2r]=As2[k][2r+1]=A
    __shared__ __align__(16) float Bs[16][128];

    const int tid = threadIdx.x;
    const int bm  = blockIdx.x * 128;
    const int bn  = blockIdx.y * 128;
    const int ty  = tid >> 4;
    const int tx  = tid & 15;

    const int arow = tid & 127;
    const int kb   = (tid >> 7) * 8;
    const int brow = tid >> 5;
    const int bcol = (tid & 31) * 4;

    unsigned long long acc[8][4];
#pragma unroll
    for (int i = 0; i < 8; i++)
#pragma unroll
        for (int j = 0; j < 4; j++) acc[i][j] = 0ull;

    const bool aok = (bm + arow) < M;
    const float* Aptr = A + (size_t)(bm + arow) * NFEAT + kb;
    const float* Wptr = W + (size_t)brow * DREP + bn + bcol;

    float4 a0 = make_float4(0.f, 0.f, 0.f, 0.f), a1 = a0;
    if (aok) { a0 = *(const float4*)(Aptr); a1 = *(const float4*)(Aptr + 4); }
    float4 b0 = *(const float4*)(Wptr);
    float4 b1 = *(const float4*)(Wptr + (size_t)8 * DREP);

    for (int k0 = 0; k0 < NFEAT; k0 += 16) {
        __syncthreads();
        *(unsigned long long*)&As2[kb + 0][2 * arow] = dup2(a0.x);
        *(unsigned long long*)&As2[kb + 1][2 * arow] = dup2(a0.y);
        *(unsigned long long*)&As2[kb + 2][2 * arow] = dup2(a0.z);
        *(unsigned long long*)&As2[kb + 3][2 * arow] = dup2(a0.w);
        *(unsigned long long*)&As2[kb + 4][2 * arow] = dup2(a1.x);
        *(unsigned long long*)&As2[kb + 5][2 * arow] = dup2(a1.y);
        *(unsigned long long*)&As2[kb + 6][2 * arow] = dup2(a1.z);
        *(unsigned long long*)&As2[kb + 7][2 * arow] = dup2(a1.w);
        *(float4*)&Bs[brow][bcol]     = b0;
        *(float4*)&Bs[brow + 8][bcol] = b1;
        __syncthreads();

        const int kn = k0 + 16;
        if (kn < NFEAT) {
            if (aok) {
                a0 = *(const float4*)(Aptr + kn);
                a1 = *(const float4*)(Aptr + kn + 4);
            }
            b0 = *(const float4*)(Wptr + (size_t)kn * DREP);
            b1 = *(const float4*)(Wptr + (size_t)(kn + 8) * DREP);
        }

#pragma unroll
        for (int kk = 0; kk < 16; kk++) {
            // ra: 8 duplicated pairs, 16-lane broadcast LDS.128 reads
            ulonglong2 ra01 = *(const ulonglong2*)&As2[kk][ty * 16];
            ulonglong2 ra23 = *(const ulonglong2*)&As2[kk][ty * 16 + 4];
            ulonglong2 ra45 = *(const ulonglong2*)&As2[kk][ty * 16 + 8];
            ulonglong2 ra67 = *(const ulonglong2*)&As2[kk][ty * 16 + 12];
            unsigned long long ra[8] = { ra01.x, ra01.y, ra23.x, ra23.y,
                                         ra45.x, ra45.y, ra67.x, ra67.y };
            ulonglong2 rbl = *(const ulonglong2*)&Bs[kk][tx * 8];
            ulonglong2 rbh = *(const ulonglong2*)&Bs[kk][tx * 8 + 4];
            unsigned long long rb[4] = { rbl.x, rbl.y, rbh.x, rbh.y };
#pragma unroll
            for (int i = 0; i < 8; i++)
#pragma unroll
                for (int j = 0; j < 4; j++) ffma2(acc[i][j], ra[i], rb[j]);
        }
    }

#pragma unroll
    for (int i = 0; i < 8; i++) {
        int row = bm + ty * 8 + i;
        if (row < M) {
#pragma unroll
            for (int j = 0; j < 4; j++) {
                float lo, hi;
                unpack2(acc[i][j], lo, hi);
                int col = bn + tx * 8 + j * 2;
                out[(size_t)row * DREP + col]     = fmaxf(lo + bias[col], 0.f);
                out[(size_t)row * DREP + col + 1] = fmaxf(hi + bias[col + 1], 0.f);
            }
        }
    }
}

// -------- layer-0: per-capsule l2norm -> fc (32x32 per capsule) -> relu -> l2norm --------
__global__ void __launch_bounds__(256) fcnorm_kernel(
    const float* __restrict__ hin, const float* __restrict__ fc_w,
    const float* __restrict__ fc_b, float* __restrict__ znorm, int N)
{
    __shared__ float wt[KCAPS * DDIM * DDIM];
    __shared__ float bs[KCAPS * DDIM];

    const int tid = threadIdx.x;
    for (int idx = tid; idx < KCAPS * DDIM * DDIM; idx += 256) {
        int k = idx >> 10;
        int o = (idx >> 5) & 31;
        int i = idx & 31;
        wt[k * 1024 + i * 32 + o] = fc_w[idx];
    }
    bs[tid] = fc_b[tid];
    __syncthreads();

    const int k = tid >> 5, lane = tid & 31;
    int node0 = blockIdx.x * 8;
    for (int nn = 0; nn < 8; nn++) {
        int node = node0 + nn;
        if (node >= N) break;
        float v = hin[(size_t)node * DREP + tid];
        float s = wsum32(v * v);
        float xn = v * rsqrtf(fmaxf(s, 1e-24f));
        float y = bs[tid];
        const float* wk = &wt[k * 1024];
#pragma unroll
        for (int i = 0; i < 32; i++) {
            float xi = __shfl_sync(0xffffffffu, xn, i);
            y = fmaf(xi, wk[i * 32 + lane], y);
        }
        y = fmaxf(y, 0.f);
        float s2 = wsum32(y * y);
        znorm[(size_t)node * DREP + tid] = y * rsqrtf(fmaxf(s2, 1e-24f));
    }
}

// ---------------- routing v4b: two nodes per CTA, shortened critical path --------
// warps = capsule k, lane = d, both nodes per thread (ILP). p/softmax phase fills
// all 256 threads. No max-subtraction in softmaxes (|p|<=1 guaranteed: z,u unit
// vectors per capsule). p_s stores exp(p). Fast rsqrt/div on the serial chain.
__global__ void __launch_bounds__(256) route_kernel(
    const float* __restrict__ znorm, const int* __restrict__ nbrs,
    const float* __restrict__ raw_param, const int* __restrict__ routit_p,
    float* __restrict__ outbuf, int out_mode, int N)
{
    __shared__ __align__(16) float z_s[2][KCAPS * MNBR * ZSTR];
    __shared__ __align__(16) float u_s[2][KCAPS * ZSTR];
    __shared__ float p_s[2][KCAPS * MNBR];    // [ns][kk*16+mm] : exp(p)
    __shared__ __align__(16) float wc_s[2][KCAPS * MNBR];

    const int tid  = threadIdx.x;
    const int k    = tid >> 5, lane = tid & 31;
    const int n0   = blockIdx.x * 2;

    int nodes[2];
    nodes[0] = n0;
    nodes[1] = (n0 + 1 < N) ? (n0 + 1) : (N - 1);   // dup-safe clamp

    const float param = 1.f / (1.f + __expf(-raw_param[0]));
    const float q = 1.f - param;
    const int rt = routit_p ? *routit_p : 6;

    // gather: 2 nodes x 16 neighbor rows into registers + smem
    float zreg[2][MNBR];
    float ub[2];
#pragma unroll
    for (int ns = 0; ns < 2; ns++) {
        const int nbase = nodes[ns] * MNBR;
#pragma unroll
        for (int m = 0; m < MNBR; m++) {
            int nb = nbrs[nbase + m];
            float v = (nb >= 0 && nb < N) ? znorm[(size_t)nb * DREP + tid] : 0.f;
            zreg[ns][m] = v;
            z_s[ns][(k * MNBR + m) * ZSTR + lane] = v;
        }
        ub[ns] = znorm[(size_t)nodes[ns] * DREP + tid];
    }

    // iteration 0: p == 0 -> p1 = 1/M, p2 = 1/K (pure registers)
    {
        const float w0 = param * (1.f / 16.f) + q * (1.f / 8.f);
#pragma unroll
        for (int ns = 0; ns < 2; ns++) {
            float a = ub[ns];
#pragma unroll
            for (int m = 0; m < MNBR; m++) a = fmaf(zreg[ns][m], w0, a);
            ub[ns] = a;
        }
    }
    __syncthreads();   // z_s visible before first p-phase

    // p-phase thread mapping: node ns, capsule kk, neighbor mm
    const int nsp = tid >> 7;
    const int kk  = (tid >> 4) & 7;
    const int mm  = tid & 15;
    const float4* zr = (const float4*)&z_s[nsp][(kk * MNBR + mm) * ZSTR];
    const float4* ur = (const float4*)&u_s[nsp][kk * ZSTR];

    for (int it = 1; it < rt; it++) {
        // normalize previous u, publish (both nodes)
#pragma unroll
        for (int ns = 0; ns < 2; ns++) {
            float s = wsum32(ub[ns] * ub[ns]);
            u_s[ns][k * ZSTR + lane] = ub[ns] * rsqrtf(fmaxf(s, 1e-24f));
        }
        __syncthreads();                       // S1

        // p[m,k] = z_m . un  (all 256 threads active); |p| <= 1
        float p = 0.f;
#pragma unroll
        for (int j = 0; j < 8; j++) {
            float4 zv = zr[j], uv = ur[j];
            p = fmaf(zv.x, uv.x, p);
            p = fmaf(zv.y, uv.y, p);
            p = fmaf(zv.z, uv.z, p);
            p = fmaf(zv.w, uv.w, p);
        }
        float e1 = __expf(p);                  // no max shift needed: p in [-1,1]
        p_s[nsp][kk * MNBR + mm] = e1;
        __syncthreads();                       // S2

        // softmax over neighbors m (p1): 16-lane shfl sum of exp
        float es = e1;
        es += __shfl_xor_sync(0xffffffffu, es, 1);
        es += __shfl_xor_sync(0xffffffffu, es, 2);
        es += __shfl_xor_sync(0xffffffffu, es, 4);
        es += __shfl_xor_sync(0xffffffffu, es, 8);

        // softmax over capsules k (p2): sum 8 pre-exponentiated values
        float es2 = 0.f;
#pragma unroll
        for (int j = 0; j < KCAPS; j++) es2 += p_s[nsp][j * MNBR + mm];

        float wc = fmaf(param, __fdividef(e1, es), q * __fdividef(e1, es2));
        wc_s[nsp][kk * MNBR + mm] = wc;
        __syncthreads();                       // S3

        // u update: pure register FMA, wc via float4 broadcast (both nodes)
#pragma unroll
        for (int ns = 0; ns < 2; ns++) {
            const float4* wr = (const float4*)&wc_s[ns][k * MNBR];
            float a = ub[ns];
#pragma unroll
            for (int j = 0; j < 4; j++) {
                float4 wv = wr[j];
                a = fmaf(zreg[ns][j * 4 + 0], wv.x, a);
                a = fmaf(zreg[ns][j * 4 + 1], wv.y, a);
                a = fmaf(zreg[ns][j * 4 + 2], wv.z, a);
                a = fmaf(zreg[ns][j * 4 + 3], wv.w, a);
            }
            ub[ns] = a;
        }
    }

#pragma unroll
    for (int ns = 0; ns < 2; ns++) {
        float v;
        if (out_mode == 0) {
            float r = fmaxf(ub[ns], 0.f);
            float s = wsum32(r * r);
            v = r * rsqrtf(fmaxf(s, 1e-24f));
        } else {
            v = ub[ns];
        }
        outbuf[(size_t)nodes[ns] * DREP + tid] = v;
    }
}

// ---------------- classifier: logit = h @ mlp_w^T + b; log_softmax; copy h ----------------
__global__ void __launch_bounds__(256) cls_kernel(
    const float* __restrict__ h, const float* __restrict__ mw,
    const float* __restrict__ mb, float* __restrict__ outLogp,
    float* __restrict__ outH, int N)
{
    __shared__ float lgs[8][17];
    const int w = threadIdx.x >> 5, lane = threadIdx.x & 31;
    const int node = blockIdx.x * 8 + w;
    if (node >= N) return;

    float hreg[8];
#pragma unroll
    for (int j = 0; j < 8; j++) hreg[j] = h[(size_t)node * DREP + j * 32 + lane];
    if (outH) {
#pragma unroll
        for (int j = 0; j < 8; j++) outH[(size_t)node * DREP + j * 32 + lane] = hreg[j];
    }

    float logit[NCLS];
#pragma unroll
    for (int c = 0; c < NCLS; c++) {
        float a = 0.f;
#pragma unroll
        for (int j = 0; j < 8; j++)
            a = fmaf(hreg[j], mw[c * DREP + j * 32 + lane], a);
        a += __shfl_xor_sync(0xffffffffu, a, 16);
        a += __shfl_xor_sync(0xffffffffu, a, 8);
        a += __shfl_xor_sync(0xffffffffu, a, 4);
        a += __shfl_xor_sync(0xffffffffu, a, 2);
        a += __shfl_xor_sync(0xffffffffu, a, 1);
        logit[c] = a + mb[c];
    }
    float mx = logit[0];
#pragma unroll
    for (int c = 1; c < NCLS; c++) mx = fmaxf(mx, logit[c]);
    float ssum = 0.f;
#pragma unroll
    for (int c = 0; c < NCLS; c++) ssum += expf(logit[c] - mx);
    float L = mx + logf(ssum);
    if (lane == 0) {
#pragma unroll
        for (int c = 0; c < NCLS; c++) lgs[w][c] = logit[c];
    }
    __syncwarp();
    if (lane < NCLS)
        outLogp[(size_t)node * NCLS + lane] = lgs[w][lane] - L;
}

__global__ void copy_kernel(const float* __restrict__ src, float* __restrict__ dst, int n)
{
    int i = blockIdx.x * blockDim.x + threadIdx.x;
    if (i < n) dst[i] = src[i];
}

// ---------------- launch ----------------
extern "C" void kernel_launch(void* const* d_in, const int* in_sizes, int n_in,
                              void* d_out, int out_size)
{
    const float* x         = (const float*)d_in[0];
    const int*   nbrs      = (const int*)  d_in[1];
    const float* pca_w     = (const float*)d_in[2];
    const float* pca_b     = (const float*)d_in[3];
    const float* raw_param = (const float*)d_in[4];
    const float* fc_w      = (const float*)d_in[5];
    const float* fc_b      = (const float*)d_in[6];
    const float* mlp_w     = (const float*)d_in[7];
    const float* mlp_b     = (const float*)d_in[8];
    const int*   routit    = (n_in > 9) ? (const int*)d_in[9] : nullptr;

    const int N = in_sizes[0] / NFEAT;

    float *bufA, *bufB, *bufC;
    cudaGetSymbolAddress((void**)&bufA, g_bufA);
    cudaGetSymbolAddress((void**)&bufB, g_bufB);
    cudaGetSymbolAddress((void**)&bufC, g_bufC);

    // 1) h0 = relu(x @ pca_w + pca_b)
    dim3 pgrid((N + 127) / 128, DREP / 128);
    pca_kernel<<<pgrid, 256>>>(x, pca_w, pca_b, bufA, N);

    // 2) layer-0 front end: l2norm -> per-capsule fc -> relu -> l2norm
    fcnorm_kernel<<<(N + 7) / 8, 256>>>(bufA, fc_w, fc_b, bufB, N);

    // 3) three routing layers (2 nodes per CTA; intermediate relu+l2norm fused)
    const int rgrid = (N + 1) / 2;
    route_kernel<<<rgrid, 256>>>(bufB, nbrs, raw_param, routit, bufA, 0, N);
    route_kernel<<<rgrid, 256>>>(bufA, nbrs, raw_param, routit, bufB, 0, N);
    route_kernel<<<rgrid, 256>>>(bufB, nbrs, raw_param, routit, bufC, 1, N);

    // 4) classifier + output assembly (adaptive to harness output layout)
    float* out = (float*)d_out;
    if (out_size == N * (NCLS + DREP)) {
        cls_kernel<<<(N + 7) / 8, 256>>>(bufC, mlp_w, mlp_b, out, out + (size_t)N * NCLS, N);
    } else if (out_size == N * NCLS) {
        cls_kernel<<<(N + 7) / 8, 256>>>(bufC, mlp_w, mlp_b, out, nullptr, N);
    } else {
        int n = N * DREP;
        copy_kernel<<<(n + 255) / 256, 256>>>(bufC, out, n);
    }
}